// round 12
// baseline (speedup 1.0000x reference)
#include <cuda_runtime.h>
#include <cuda_bf16.h>
#include <math.h>
#include <stdint.h>

#define BATCH 2
#define SEQ   2048
#define HID   1024
#define NHEAD 16
#define HDIM  64
#define TOK   (BATCH*SEQ)
#define EPS_LN 1e-12f

typedef __nv_bfloat16  bf16;
typedef __nv_bfloat162 bf162;

// ---------------- scratch (device globals; no runtime allocation) ------------
__device__ bf16 g_xln[TOK * HID];      // LN output (bf16)
__device__ bf16 g_q[TOK * HID];        // Q [B,NH,S,HD]
__device__ bf16 g_k[TOK * HID];        // K [B,NH,S,HD]
__device__ bf16 g_v[TOK * HID];        // V [B,NH,S,HD]
__device__ bf16 g_ctx[TOK * HID];      // attention ctx [B,S,H]
__device__ bf16 g_wb[4 * HID * HID];   // bf16 weights: wq wk wv wo

// ---------------- helpers ----------------------------------------------------
__device__ __forceinline__ uint32_t smem_u32(const void* p) {
    return (uint32_t)__cvta_generic_to_shared(p);
}
__device__ __forceinline__ void ldsm_x4(uint32_t addr, uint32_t* r) {
    asm volatile("ldmatrix.sync.aligned.m8n8.x4.shared.b16 {%0,%1,%2,%3}, [%4];"
                 : "=r"(r[0]), "=r"(r[1]), "=r"(r[2]), "=r"(r[3]) : "r"(addr));
}
__device__ __forceinline__ void ldsm_x4_t(uint32_t addr, uint32_t* r) {
    asm volatile("ldmatrix.sync.aligned.m8n8.x4.trans.shared.b16 {%0,%1,%2,%3}, [%4];"
                 : "=r"(r[0]), "=r"(r[1]), "=r"(r[2]), "=r"(r[3]) : "r"(addr));
}
__device__ __forceinline__ void cp16(uint32_t dst, const void* src) {
    asm volatile("cp.async.cg.shared.global [%0], [%1], 16;" :: "r"(dst), "l"(src));
}
__device__ __forceinline__ void cp_commit() { asm volatile("cp.async.commit_group;"); }
template<int N> __device__ __forceinline__ void cp_wait() {
    asm volatile("cp.async.wait_group %0;" :: "n"(N));
}
__device__ __forceinline__ void mma_bf16(float* c, const uint32_t* a,
                                         uint32_t b0, uint32_t b1) {
    asm volatile(
        "mma.sync.aligned.m16n8k16.row.col.f32.bf16.bf16.f32 "
        "{%0,%1,%2,%3}, {%4,%5,%6,%7}, {%8,%9}, {%0,%1,%2,%3};"
        : "+f"(c[0]), "+f"(c[1]), "+f"(c[2]), "+f"(c[3])
        : "r"(a[0]), "r"(a[1]), "r"(a[2]), "r"(a[3]), "r"(b0), "r"(b1));
}
__device__ __forceinline__ uint32_t packbf(float x, float y) {
    bf162 t = __floats2bfloat162_rn(x, y);
    return *reinterpret_cast<uint32_t*>(&t);
}

// ============ fused prologue: LN (blocks 0..4095) + weight rounding ==========
__global__ __launch_bounds__(256)
void prologue(const float* __restrict__ x,
              const float* __restrict__ gamma,
              const float* __restrict__ beta,
              const float* __restrict__ wq, const float* __restrict__ wk,
              const float* __restrict__ wv, const float* __restrict__ wo)
{
    const int t = threadIdx.x;
    if (blockIdx.x < TOK) {
        const int row = blockIdx.x;
        float4 v = reinterpret_cast<const float4*>(x + (size_t)row * HID)[t];

        float s1 = v.x + v.y + v.z + v.w;
        float s2 = v.x*v.x + v.y*v.y + v.z*v.z + v.w*v.w;
        #pragma unroll
        for (int o = 16; o; o >>= 1) {
            s1 += __shfl_xor_sync(0xffffffffu, s1, o);
            s2 += __shfl_xor_sync(0xffffffffu, s2, o);
        }
        __shared__ float red1[8], red2[8];
        const int wid = t >> 5, lane = t & 31;
        if (lane == 0) { red1[wid] = s1; red2[wid] = s2; }
        __syncthreads();
        float tot = 0.f, tot2 = 0.f;
        #pragma unroll
        for (int i = 0; i < 8; i++) { tot += red1[i]; tot2 += red2[i]; }

        const float mu   = tot * (1.0f / HID);
        const float var  = tot2 * (1.0f / HID) - mu * mu;
        const float rstd = rsqrtf(var + EPS_LN);

        const float4 g = reinterpret_cast<const float4*>(gamma)[t];
        const float4 b = reinterpret_cast<const float4*>(beta)[t];
        bf162* out2 = reinterpret_cast<bf162*>(g_xln + (size_t)row * HID) + 2 * t;
        out2[0] = __floats2bfloat162_rn((v.x - mu) * rstd * g.x + b.x,
                                        (v.y - mu) * rstd * g.y + b.y);
        out2[1] = __floats2bfloat162_rn((v.z - mu) * rstd * g.z + b.z,
                                        (v.w - mu) * rstd * g.w + b.w);
    } else {
        const int idx = blockIdx.x - TOK;
        const int m   = idx >> 9;
        const float* src = (m == 0) ? wq : (m == 1) ? wk : (m == 2) ? wv : wo;
        bf16* dst = g_wb + (size_t)m * HID * HID;
        const int e = (idx & 511) * 2048 + t * 8;
        float4 v0 = *reinterpret_cast<const float4*>(src + e);
        float4 v1 = *reinterpret_cast<const float4*>(src + e + 4);
        bf162* d2 = reinterpret_cast<bf162*>(dst + e);
        d2[0] = __floats2bfloat162_rn(v0.x, v0.y);
        d2[1] = __floats2bfloat162_rn(v0.z, v0.w);
        d2[2] = __floats2bfloat162_rn(v1.x, v1.y);
        d2[3] = __floats2bfloat162_rn(v1.z, v1.w);
    }
}

// ============================ bf16 GEMM (NT) — R8 ============================
// 128x128 CTA, 8 warps (2M x 4N), warp tile 64x32, K-tile 64, 3-stage pipeline.
#define GSTR 72
#define GEMM_STAGE_BYTES (2 * 128 * 144)
#define GEMM_SMEM_BYTES  (3 * GEMM_STAGE_BYTES)

__device__ __forceinline__ void gemm_prefetch(
    uint32_t stB, const bf16* __restrict__ A, const bf16* __restrict__ B,
    int bm0, int bn0, int kt, int t)
{
    #pragma unroll
    for (int u = 0; u < 4; ++u) {
        const int f = t + 256 * u, row = f >> 3, ch = f & 7;
        cp16(stB + row * 144 + ch * 16,
             A + (size_t)(bm0 + row) * HID + kt * 64 + ch * 8);
        cp16(stB + 128 * 144 + row * 144 + ch * 16,
             B + (size_t)(bn0 + row) * HID + kt * 64 + ch * 8);
    }
    cp_commit();
}

__device__ __forceinline__ void gemm_tile_compute(
    uint32_t stB, const int* offA, const int* offB, float acc[4][4][4])
{
    const uint32_t aB = stB, bB = stB + 128 * 144;
    #pragma unroll
    for (int kk = 0; kk < 4; ++kk) {
        uint32_t a[4][4], b[2][4];
        #pragma unroll
        for (int mi = 0; mi < 4; ++mi) ldsm_x4(aB + offA[mi] + kk * 32, a[mi]);
        #pragma unroll
        for (int p = 0; p < 2; ++p)   ldsm_x4(bB + offB[p] + kk * 32, b[p]);
        #pragma unroll
        for (int mi = 0; mi < 4; ++mi)
            #pragma unroll
            for (int ni = 0; ni < 4; ++ni)
                mma_bf16(acc[mi][ni], a[mi],
                         b[ni >> 1][(ni & 1) * 2], b[ni >> 1][(ni & 1) * 2 + 1]);
    }
}

__device__ __forceinline__ void gemm_mainloop(
    const bf16* __restrict__ Ag, const bf16* __restrict__ Bg,
    int bm0, int bn0, int t, const int* offA, const int* offB,
    uint32_t smb, float acc[4][4][4])
{
    gemm_prefetch(smb + 0 * GEMM_STAGE_BYTES, Ag, Bg, bm0, bn0, 0, t);
    gemm_prefetch(smb + 1 * GEMM_STAGE_BYTES, Ag, Bg, bm0, bn0, 1, t);
    #pragma unroll 1
    for (int kt = 0; kt < 16; ++kt) {
        if (kt < 15) cp_wait<1>(); else cp_wait<0>();
        __syncthreads();
        if (kt + 2 < 16)
            gemm_prefetch(smb + ((kt + 2) % 3) * GEMM_STAGE_BYTES,
                          Ag, Bg, bm0, bn0, kt + 2, t);
        gemm_tile_compute(smb + (kt % 3) * GEMM_STAGE_BYTES, offA, offB, acc);
    }
}

// QKV projection
__global__ __launch_bounds__(256)
void gemm_qkv(const float* __restrict__ bq, const float* __restrict__ bk,
              const float* __restrict__ bv)
{
    extern __shared__ char smraw[];
    const uint32_t smb = smem_u32(smraw);

    const int z = blockIdx.z;
    const bf16* W = g_wb + (size_t)z * HID * HID;
    const float* bias = (z == 0) ? bq : (z == 1) ? bk : bv;
    bf16* out = (z == 0) ? g_q : (z == 1) ? g_k : g_v;

    const int t = threadIdx.x, w = t >> 5, lane = t & 31;
    const int r = lane & 7, hb = (lane >> 3) & 1, hc = lane >> 4;
    const int wm = (w & 1) * 64, wn = (w >> 1) * 32;
    const int bm0 = blockIdx.y * 128, bn0 = blockIdx.x * 128;

    int offA[4], offB[2];
    #pragma unroll
    for (int mi = 0; mi < 4; ++mi)
        offA[mi] = (wm + mi * 16 + r + hb * 8) * 144 + hc * 16;
    #pragma unroll
    for (int p = 0; p < 2; ++p)
        offB[p] = (wn + p * 16 + hc * 8 + r) * 144 + hb * 16;

    float acc[4][4][4];
    #pragma unroll
    for (int mi = 0; mi < 4; ++mi)
        #pragma unroll
        for (int ni = 0; ni < 4; ++ni)
            #pragma unroll
            for (int cc = 0; cc < 4; ++cc) acc[mi][ni][cc] = 0.f;

    gemm_mainloop(g_xln, W, bm0, bn0, t, offA, offB, smb, acc);

    const int g = lane >> 2, tig = lane & 3;
    #pragma unroll
    for (int mi = 0; mi < 4; ++mi) {
        #pragma unroll
        for (int ni = 0; ni < 4; ++ni) {
            const int j = bn0 + wn + ni * 8 + 2 * tig;
            const int h = j >> 6, d = j & 63;
            #pragma unroll
            for (int half = 0; half < 2; ++half) {
                const int i = bm0 + wm + mi * 16 + g + half * 8;
                const int bb = i >> 11, s = i & 2047;
                const float v0 = acc[mi][ni][half * 2 + 0] + bias[j];
                const float v1 = acc[mi][ni][half * 2 + 1] + bias[j + 1];
                *reinterpret_cast<bf162*>(
                    out + (((size_t)(bb * NHEAD + h)) * SEQ + s) * HDIM + d) =
                    __floats2bfloat162_rn(v0, v1);
            }
        }
    }
}

// O projection + bias + residual (fp32 out)
__global__ __launch_bounds__(256)
void gemm_out(const float* __restrict__ bo, const float* __restrict__ resid,
              float* __restrict__ out)
{
    extern __shared__ char smraw[];
    const uint32_t smb = smem_u32(smraw);
    const bf16* W = g_wb + (size_t)3 * HID * HID;

    const int t = threadIdx.x, w = t >> 5, lane = t & 31;
    const int r = lane & 7, hb = (lane >> 3) & 1, hc = lane >> 4;
    const int wm = (w & 1) * 64, wn = (w >> 1) * 32;
    const int bm0 = blockIdx.y * 128, bn0 = blockIdx.x * 128;

    int offA[4], offB[2];
    #pragma unroll
    for (int mi = 0; mi < 4; ++mi)
        offA[mi] = (wm + mi * 16 + r + hb * 8) * 144 + hc * 16;
    #pragma unroll
    for (int p = 0; p < 2; ++p)
        offB[p] = (wn + p * 16 + hc * 8 + r) * 144 + hb * 16;

    float acc[4][4][4];
    #pragma unroll
    for (int mi = 0; mi < 4; ++mi)
        #pragma unroll
        for (int ni = 0; ni < 4; ++ni)
            #pragma unroll
            for (int cc = 0; cc < 4; ++cc) acc[mi][ni][cc] = 0.f;

    gemm_mainloop(g_ctx, W, bm0, bn0, t, offA, offB, smb, acc);

    const int g = lane >> 2, tig = lane & 3;
    #pragma unroll
    for (int mi = 0; mi < 4; ++mi) {
        #pragma unroll
        for (int ni = 0; ni < 4; ++ni) {
            const int j = bn0 + wn + ni * 8 + 2 * tig;
            #pragma unroll
            for (int half = 0; half < 2; ++half) {
                const int i = bm0 + wm + mi * 16 + g + half * 8;
                const float2 rz = *reinterpret_cast<const float2*>(
                    resid + (size_t)i * HID + j);
                float2 o;
                o.x = acc[mi][ni][half * 2 + 0] + bo[j]     + rz.x;
                o.y = acc[mi][ni][half * 2 + 1] + bo[j + 1] + rz.y;
                *reinterpret_cast<float2*>(out + (size_t)i * HID + j) = o;
            }
        }
    }
}

// ======================= bf16 flash attention ================================
// CTA: 64 q-rows x one (b,h), 4 warps x 16 q-rows. 2-stage KV double-buffer.
// XOR-swizzled 128B-stride tiles (swizzle<3,4,3>) + mask via __ldg:
// smem = 8KB Q + 2x16KB KV = 40KB exactly -> 5 CTA/SM, capacity 740 CTAs.
#define ATTN_STAGE_BYTES (2 * 64 * 128)           // K tile + V tile
#define ATTN_SMEM_BYTES  (64 * 128 + 2 * ATTN_STAGE_BYTES)   // 40960
#define LOG2E 1.44269504f

__global__ __launch_bounds__(128)
void attn_bf16(const float* __restrict__ mask)
{
    extern __shared__ char smraw[];
    const uint32_t qB  = smem_u32(smraw);            // Q [64 rows x 128B], swizzled
    const uint32_t kvB = qB + 64 * 128;              // 2 x (K 8KB + V 8KB)

    const int qt = blockIdx.x, bh = blockIdx.y;
    const int b  = bh >> 4, h = bh & 15;
    const int q0 = qt * 64;
    const bf16* Qg = g_q + (size_t)bh * SEQ * HDIM + (size_t)q0 * HDIM;
    const bf16* Kg = g_k + (size_t)bh * SEQ * HDIM;
    const bf16* Vg = g_v + (size_t)bh * SEQ * HDIM;
    const float* mk = mask + (size_t)b * SEQ;

    const int t = threadIdx.x, w = t >> 5, lane = t & 31;
    const int g = lane >> 2, tig = lane & 3;
    const int r = lane & 7, hb = (lane >> 3) & 1, hc = lane >> 4;

    // ---- swizzled store: dst = base + row*128 + ((ch ^ (row&7))*16) ----
    #pragma unroll
    for (int u = 0; u < 4; ++u) {
        const int f = t + 128 * u, row = f >> 3, ch = f & 7;
        cp16(qB + row * 128 + ((ch ^ (row & 7)) << 4),
             Qg + (size_t)row * HDIM + ch * 8);
    }
    cp_commit();

    auto kv_prefetch = [&](int kt, int s) {
        const uint32_t sB = kvB + s * ATTN_STAGE_BYTES;
        #pragma unroll
        for (int u = 0; u < 4; ++u) {
            const int f = t + 128 * u, row = f >> 3, ch = f & 7;
            const uint32_t sw = row * 128 + ((ch ^ (row & 7)) << 4);
            cp16(sB + sw,        Kg + (size_t)(kt * 64 + row) * HDIM + ch * 8);
            cp16(sB + 8192 + sw, Vg + (size_t)(kt * 64 + row) * HDIM + ch * 8);
        }
        cp_commit();
    };

    kv_prefetch(0, 0);
    kv_prefetch(1, 1);

    // ---- swizzled fragment offsets (all fragment rows have row&7 == r) ----
    // Q/P rows: row = w*16 + r + hb*8, col chunk = hc + 2*kk
    const int baseQ = (w * 16 + r + hb * 8) * 128;
    // K rows (n-dim): row = p*16 + hc*8 + r, col chunk = hb + 2*kk
    int baseK[4];
    #pragma unroll
    for (int p = 0; p < 4; ++p) baseK[p] = (p * 16 + hc * 8 + r) * 128;
    // V rows (k-dim, trans): row = r + hb*8 + kk*16, col chunk = hc + 2*dj
    const int baseV = (r + hb * 8) * 128;
    int colQV[4], colK[4];
    #pragma unroll
    for (int k4 = 0; k4 < 4; ++k4) {
        colQV[k4] = (((hc + 2 * k4) ^ r) << 4);   // Q cols (kk) and V cols (dj)
        colK[k4]  = (((hb + 2 * k4) ^ r) << 4);   // K cols (kk)
    }

    cp_wait<2>();
    __syncthreads();
    uint32_t qf[4][4];
    #pragma unroll
    for (int kk = 0; kk < 4; ++kk) ldsm_x4(qB + baseQ + colQV[kk], qf[kk]);

    float oacc[8][4];
    #pragma unroll
    for (int di = 0; di < 8; ++di)
        #pragma unroll
        for (int cc = 0; cc < 4; ++cc) oacc[di][cc] = 0.f;
    float lrow[2] = { 0.f, 0.f };
    const float SC = 0.125f * LOG2E;

    #pragma unroll 1
    for (int kt = 0; kt < SEQ / 64; ++kt) {
        if (kt < 31) cp_wait<1>(); else cp_wait<0>();
        __syncthreads();

        const int cur = kt & 1;
        const uint32_t kB = kvB + cur * ATTN_STAGE_BYTES;
        const uint32_t vB = kB + 8192;

        // ---- S = Q K^T ----
        float sacc[8][4];
        #pragma unroll
        for (int ni = 0; ni < 8; ++ni)
            #pragma unroll
            for (int cc = 0; cc < 4; ++cc) sacc[ni][cc] = 0.f;

        #pragma unroll
        for (int kk = 0; kk < 4; ++kk) {
            uint32_t kb[4][4];
            #pragma unroll
            for (int p = 0; p < 4; ++p) ldsm_x4(kB + baseK[p] + colK[kk], kb[p]);
            #pragma unroll
            for (int ni = 0; ni < 8; ++ni)
                mma_bf16(sacc[ni], qf[kk],
                         kb[ni >> 1][(ni & 1) * 2], kb[ni >> 1][(ni & 1) * 2 + 1]);
        }

        // ---- softmax numerator (log2 domain); mask via __ldg (L1-resident) ----
        #pragma unroll
        for (int rr = 0; rr < 2; ++rr) {
            float rs = 0.f;
            #pragma unroll
            for (int ni = 0; ni < 8; ++ni) {
                const float2 mv = __ldg(reinterpret_cast<const float2*>(
                    mk + kt * 64 + ni * 8 + 2 * tig));
                float v0 = fminf(fmaf(sacc[ni][rr * 2 + 0], SC, mv.x * LOG2E), 80.f);
                float v1 = fminf(fmaf(sacc[ni][rr * 2 + 1], SC, mv.y * LOG2E), 80.f);
                const float p0 = exp2f(v0);
                const float p1 = exp2f(v1);
                sacc[ni][rr * 2 + 0] = p0;
                sacc[ni][rr * 2 + 1] = p1;
                rs += p0 + p1;
            }
            rs += __shfl_xor_sync(0xffffffffu, rs, 1);
            rs += __shfl_xor_sync(0xffffffffu, rs, 2);
            lrow[rr] += rs;
        }

        // ---- O += P V  (S C-frags repacked as PV A-frags, V via ldsm.trans) ----
        #pragma unroll
        for (int kk = 0; kk < 4; ++kk) {
            uint32_t a[4], vt[4][4];
            a[0] = packbf(sacc[2 * kk][0],     sacc[2 * kk][1]);
            a[1] = packbf(sacc[2 * kk][2],     sacc[2 * kk][3]);
            a[2] = packbf(sacc[2 * kk + 1][0], sacc[2 * kk + 1][1]);
            a[3] = packbf(sacc[2 * kk + 1][2], sacc[2 * kk + 1][3]);
            #pragma unroll
            for (int dj = 0; dj < 4; ++dj)
                ldsm_x4_t(vB + baseV + kk * 2048 + colQV[dj], vt[dj]);
            #pragma unroll
            for (int di = 0; di < 8; ++di)
                mma_bf16(oacc[di], a,
                         vt[di >> 1][(di & 1) * 2], vt[di >> 1][(di & 1) * 2 + 1]);
        }

        __syncthreads();
        if (kt + 2 < 32) kv_prefetch(kt + 2, cur);
    }

    // ---- epilogue: ctx bf16 [B,S,H], column block h*64 ----
    const float inv0 = 1.0f / lrow[0];
    const float inv1 = 1.0f / lrow[1];
    const int row0 = q0 + w * 16 + g;
    bf16* base0 = g_ctx + ((size_t)(b * SEQ + row0)) * HID + h * 64;
    bf16* base1 = g_ctx + ((size_t)(b * SEQ + row0 + 8)) * HID + h * 64;
    #pragma unroll
    for (int di = 0; di < 8; ++di) {
        const int c = di * 8 + 2 * tig;
        *reinterpret_cast<bf162*>(base0 + c) =
            __floats2bfloat162_rn(oacc[di][0] * inv0, oacc[di][1] * inv0);
        *reinterpret_cast<bf162*>(base1 + c) =
            __floats2bfloat162_rn(oacc[di][2] * inv1, oacc[di][3] * inv1);
    }
}

// ================================ launch =====================================
extern "C" void kernel_launch(void* const* d_in, const int* in_sizes, int n_in,
                              void* d_out, int out_size)
{
    const float* hs    = (const float*)d_in[0];
    const float* mask  = (const float*)d_in[1];
    const float* wq    = (const float*)d_in[2];
    const float* bq    = (const float*)d_in[3];
    const float* wk    = (const float*)d_in[4];
    const float* bk    = (const float*)d_in[5];
    const float* wv    = (const float*)d_in[6];
    const float* bv    = (const float*)d_in[7];
    const float* wo    = (const float*)d_in[8];
    const float* bo    = (const float*)d_in[9];
    const float* gamma = (const float*)d_in[10];
    const float* beta  = (const float*)d_in[11];
    float* out = (float*)d_out;

    cudaFuncSetAttribute(gemm_qkv, cudaFuncAttributeMaxDynamicSharedMemorySize,
                         GEMM_SMEM_BYTES);
    cudaFuncSetAttribute(gemm_out, cudaFuncAttributeMaxDynamicSharedMemorySize,
                         GEMM_SMEM_BYTES);
    cudaFuncSetAttribute(attn_bf16, cudaFuncAttributeMaxDynamicSharedMemorySize,
                         ATTN_SMEM_BYTES);

    // 0+1. fused: LayerNorm + weight rounding
    prologue<<<TOK + 2048, 256>>>(hs, gamma, beta, wq, wk, wv, wo);

    // 2. fused Q/K/V projections (R8 8-warp config)
    dim3 gq(HID / 128, TOK / 128, 3);
    gemm_qkv<<<gq, 256, GEMM_SMEM_BYTES>>>(bq, bk, bv);

    // 3. attention (64-row q-tiles, 5 CTA/SM target)
    dim3 ga(SEQ / 64, BATCH * NHEAD);   // (32, 32) = 1024 CTAs
    attn_bf16<<<ga, 128, ATTN_SMEM_BYTES>>>(mask);

    // 4. output projection + bias + residual
    dim3 gg(HID / 128, TOK / 128);
    gemm_out<<<gg, 256, GEMM_SMEM_BYTES>>>(bo, hs, out);
}

// round 14
// speedup vs baseline: 1.1523x; 1.1523x over previous
#include <cuda_runtime.h>
#include <cuda_bf16.h>
#include <math.h>
#include <stdint.h>

#define BATCH 2
#define SEQ   2048
#define HID   1024
#define NHEAD 16
#define HDIM  64
#define TOK   (BATCH*SEQ)
#define EPS_LN 1e-12f

typedef __nv_bfloat16  bf16;
typedef __nv_bfloat162 bf162;

// ---------------- scratch (device globals; no runtime allocation) ------------
__device__ bf16 g_xln[TOK * HID];      // LN output (bf16)
__device__ bf16 g_q[TOK * HID];        // Q [B,NH,S,HD]
__device__ bf16 g_k[TOK * HID];        // K [B,NH,S,HD]
__device__ bf16 g_v[TOK * HID];        // V [B,NH,S,HD]
__device__ bf16 g_ctx[TOK * HID];      // attention ctx [B,S,H]
__device__ bf16 g_wb[4 * HID * HID];   // bf16 weights: wq wk wv wo

// ---------------- helpers ----------------------------------------------------
__device__ __forceinline__ uint32_t smem_u32(const void* p) {
    return (uint32_t)__cvta_generic_to_shared(p);
}
__device__ __forceinline__ void ldsm_x4(uint32_t addr, uint32_t* r) {
    asm volatile("ldmatrix.sync.aligned.m8n8.x4.shared.b16 {%0,%1,%2,%3}, [%4];"
                 : "=r"(r[0]), "=r"(r[1]), "=r"(r[2]), "=r"(r[3]) : "r"(addr));
}
__device__ __forceinline__ void ldsm_x4_t(uint32_t addr, uint32_t* r) {
    asm volatile("ldmatrix.sync.aligned.m8n8.x4.trans.shared.b16 {%0,%1,%2,%3}, [%4];"
                 : "=r"(r[0]), "=r"(r[1]), "=r"(r[2]), "=r"(r[3]) : "r"(addr));
}
__device__ __forceinline__ void cp16(uint32_t dst, const void* src) {
    asm volatile("cp.async.cg.shared.global [%0], [%1], 16;" :: "r"(dst), "l"(src));
}
__device__ __forceinline__ void cp_commit() { asm volatile("cp.async.commit_group;"); }
template<int N> __device__ __forceinline__ void cp_wait() {
    asm volatile("cp.async.wait_group %0;" :: "n"(N));
}
__device__ __forceinline__ void mma_bf16(float* c, const uint32_t* a,
                                         uint32_t b0, uint32_t b1) {
    asm volatile(
        "mma.sync.aligned.m16n8k16.row.col.f32.bf16.bf16.f32 "
        "{%0,%1,%2,%3}, {%4,%5,%6,%7}, {%8,%9}, {%0,%1,%2,%3};"
        : "+f"(c[0]), "+f"(c[1]), "+f"(c[2]), "+f"(c[3])
        : "r"(a[0]), "r"(a[1]), "r"(a[2]), "r"(a[3]), "r"(b0), "r"(b1));
}
__device__ __forceinline__ uint32_t packbf(float x, float y) {
    bf162 t = __floats2bfloat162_rn(x, y);
    return *reinterpret_cast<uint32_t*>(&t);
}

// ============ fused prologue: LN (blocks 0..4095) + weight rounding ==========
__global__ __launch_bounds__(256)
void prologue(const float* __restrict__ x,
              const float* __restrict__ gamma,
              const float* __restrict__ beta,
              const float* __restrict__ wq, const float* __restrict__ wk,
              const float* __restrict__ wv, const float* __restrict__ wo)
{
    const int t = threadIdx.x;
    if (blockIdx.x < TOK) {
        const int row = blockIdx.x;
        float4 v = reinterpret_cast<const float4*>(x + (size_t)row * HID)[t];

        float s1 = v.x + v.y + v.z + v.w;
        float s2 = v.x*v.x + v.y*v.y + v.z*v.z + v.w*v.w;
        #pragma unroll
        for (int o = 16; o; o >>= 1) {
            s1 += __shfl_xor_sync(0xffffffffu, s1, o);
            s2 += __shfl_xor_sync(0xffffffffu, s2, o);
        }
        __shared__ float red1[8], red2[8];
        const int wid = t >> 5, lane = t & 31;
        if (lane == 0) { red1[wid] = s1; red2[wid] = s2; }
        __syncthreads();
        float tot = 0.f, tot2 = 0.f;
        #pragma unroll
        for (int i = 0; i < 8; i++) { tot += red1[i]; tot2 += red2[i]; }

        const float mu   = tot * (1.0f / HID);
        const float var  = tot2 * (1.0f / HID) - mu * mu;
        const float rstd = rsqrtf(var + EPS_LN);

        const float4 g = reinterpret_cast<const float4*>(gamma)[t];
        const float4 b = reinterpret_cast<const float4*>(beta)[t];
        bf162* out2 = reinterpret_cast<bf162*>(g_xln + (size_t)row * HID) + 2 * t;
        out2[0] = __floats2bfloat162_rn((v.x - mu) * rstd * g.x + b.x,
                                        (v.y - mu) * rstd * g.y + b.y);
        out2[1] = __floats2bfloat162_rn((v.z - mu) * rstd * g.z + b.z,
                                        (v.w - mu) * rstd * g.w + b.w);
    } else {
        const int idx = blockIdx.x - TOK;
        const int m   = idx >> 9;
        const float* src = (m == 0) ? wq : (m == 1) ? wk : (m == 2) ? wv : wo;
        bf16* dst = g_wb + (size_t)m * HID * HID;
        const int e = (idx & 511) * 2048 + t * 8;
        float4 v0 = *reinterpret_cast<const float4*>(src + e);
        float4 v1 = *reinterpret_cast<const float4*>(src + e + 4);
        bf162* d2 = reinterpret_cast<bf162*>(dst + e);
        d2[0] = __floats2bfloat162_rn(v0.x, v0.y);
        d2[1] = __floats2bfloat162_rn(v0.z, v0.w);
        d2[2] = __floats2bfloat162_rn(v1.x, v1.y);
        d2[3] = __floats2bfloat162_rn(v1.z, v1.w);
    }
}

// ============================ bf16 GEMM (NT) — R8 ============================
// 128x128 CTA, 8 warps (2M x 4N), warp tile 64x32, K-tile 64, 3-stage pipeline.
#define GSTR 72
#define GEMM_STAGE_BYTES (2 * 128 * 144)
#define GEMM_SMEM_BYTES  (3 * GEMM_STAGE_BYTES)

__device__ __forceinline__ void gemm_prefetch(
    uint32_t stB, const bf16* __restrict__ A, const bf16* __restrict__ B,
    int bm0, int bn0, int kt, int t)
{
    #pragma unroll
    for (int u = 0; u < 4; ++u) {
        const int f = t + 256 * u, row = f >> 3, ch = f & 7;
        cp16(stB + row * 144 + ch * 16,
             A + (size_t)(bm0 + row) * HID + kt * 64 + ch * 8);
        cp16(stB + 128 * 144 + row * 144 + ch * 16,
             B + (size_t)(bn0 + row) * HID + kt * 64 + ch * 8);
    }
    cp_commit();
}

__device__ __forceinline__ void gemm_tile_compute(
    uint32_t stB, const int* offA, const int* offB, float acc[4][4][4])
{
    const uint32_t aB = stB, bB = stB + 128 * 144;
    #pragma unroll
    for (int kk = 0; kk < 4; ++kk) {
        uint32_t a[4][4], b[2][4];
        #pragma unroll
        for (int mi = 0; mi < 4; ++mi) ldsm_x4(aB + offA[mi] + kk * 32, a[mi]);
        #pragma unroll
        for (int p = 0; p < 2; ++p)   ldsm_x4(bB + offB[p] + kk * 32, b[p]);
        #pragma unroll
        for (int mi = 0; mi < 4; ++mi)
            #pragma unroll
            for (int ni = 0; ni < 4; ++ni)
                mma_bf16(acc[mi][ni], a[mi],
                         b[ni >> 1][(ni & 1) * 2], b[ni >> 1][(ni & 1) * 2 + 1]);
    }
}

__device__ __forceinline__ void gemm_mainloop(
    const bf16* __restrict__ Ag, const bf16* __restrict__ Bg,
    int bm0, int bn0, int t, const int* offA, const int* offB,
    uint32_t smb, float acc[4][4][4])
{
    gemm_prefetch(smb + 0 * GEMM_STAGE_BYTES, Ag, Bg, bm0, bn0, 0, t);
    gemm_prefetch(smb + 1 * GEMM_STAGE_BYTES, Ag, Bg, bm0, bn0, 1, t);
    #pragma unroll 1
    for (int kt = 0; kt < 16; ++kt) {
        if (kt < 15) cp_wait<1>(); else cp_wait<0>();
        __syncthreads();
        if (kt + 2 < 16)
            gemm_prefetch(smb + ((kt + 2) % 3) * GEMM_STAGE_BYTES,
                          Ag, Bg, bm0, bn0, kt + 2, t);
        gemm_tile_compute(smb + (kt % 3) * GEMM_STAGE_BYTES, offA, offB, acc);
    }
}

// QKV projection
__global__ __launch_bounds__(256)
void gemm_qkv(const float* __restrict__ bq, const float* __restrict__ bk,
              const float* __restrict__ bv)
{
    extern __shared__ char smraw[];
    const uint32_t smb = smem_u32(smraw);

    const int z = blockIdx.z;
    const bf16* W = g_wb + (size_t)z * HID * HID;
    const float* bias = (z == 0) ? bq : (z == 1) ? bk : bv;
    bf16* out = (z == 0) ? g_q : (z == 1) ? g_k : g_v;

    const int t = threadIdx.x, w = t >> 5, lane = t & 31;
    const int r = lane & 7, hb = (lane >> 3) & 1, hc = lane >> 4;
    const int wm = (w & 1) * 64, wn = (w >> 1) * 32;
    const int bm0 = blockIdx.y * 128, bn0 = blockIdx.x * 128;

    int offA[4], offB[2];
    #pragma unroll
    for (int mi = 0; mi < 4; ++mi)
        offA[mi] = (wm + mi * 16 + r + hb * 8) * 144 + hc * 16;
    #pragma unroll
    for (int p = 0; p < 2; ++p)
        offB[p] = (wn + p * 16 + hc * 8 + r) * 144 + hb * 16;

    float acc[4][4][4];
    #pragma unroll
    for (int mi = 0; mi < 4; ++mi)
        #pragma unroll
        for (int ni = 0; ni < 4; ++ni)
            #pragma unroll
            for (int cc = 0; cc < 4; ++cc) acc[mi][ni][cc] = 0.f;

    gemm_mainloop(g_xln, W, bm0, bn0, t, offA, offB, smb, acc);

    const int g = lane >> 2, tig = lane & 3;
    #pragma unroll
    for (int mi = 0; mi < 4; ++mi) {
        #pragma unroll
        for (int ni = 0; ni < 4; ++ni) {
            const int j = bn0 + wn + ni * 8 + 2 * tig;
            const int h = j >> 6, d = j & 63;
            #pragma unroll
            for (int half = 0; half < 2; ++half) {
                const int i = bm0 + wm + mi * 16 + g + half * 8;
                const int bb = i >> 11, s = i & 2047;
                const float v0 = acc[mi][ni][half * 2 + 0] + bias[j];
                const float v1 = acc[mi][ni][half * 2 + 1] + bias[j + 1];
                *reinterpret_cast<bf162*>(
                    out + (((size_t)(bb * NHEAD + h)) * SEQ + s) * HDIM + d) =
                    __floats2bfloat162_rn(v0, v1);
            }
        }
    }
}

// O projection + bias + residual (fp32 out)
__global__ __launch_bounds__(256)
void gemm_out(const float* __restrict__ bo, const float* __restrict__ resid,
              float* __restrict__ out)
{
    extern __shared__ char smraw[];
    const uint32_t smb = smem_u32(smraw);
    const bf16* W = g_wb + (size_t)3 * HID * HID;

    const int t = threadIdx.x, w = t >> 5, lane = t & 31;
    const int r = lane & 7, hb = (lane >> 3) & 1, hc = lane >> 4;
    const int wm = (w & 1) * 64, wn = (w >> 1) * 32;
    const int bm0 = blockIdx.y * 128, bn0 = blockIdx.x * 128;

    int offA[4], offB[2];
    #pragma unroll
    for (int mi = 0; mi < 4; ++mi)
        offA[mi] = (wm + mi * 16 + r + hb * 8) * 144 + hc * 16;
    #pragma unroll
    for (int p = 0; p < 2; ++p)
        offB[p] = (wn + p * 16 + hc * 8 + r) * 144 + hb * 16;

    float acc[4][4][4];
    #pragma unroll
    for (int mi = 0; mi < 4; ++mi)
        #pragma unroll
        for (int ni = 0; ni < 4; ++ni)
            #pragma unroll
            for (int cc = 0; cc < 4; ++cc) acc[mi][ni][cc] = 0.f;

    gemm_mainloop(g_ctx, W, bm0, bn0, t, offA, offB, smb, acc);

    const int g = lane >> 2, tig = lane & 3;
    #pragma unroll
    for (int mi = 0; mi < 4; ++mi) {
        #pragma unroll
        for (int ni = 0; ni < 4; ++ni) {
            const int j = bn0 + wn + ni * 8 + 2 * tig;
            #pragma unroll
            for (int half = 0; half < 2; ++half) {
                const int i = bm0 + wm + mi * 16 + g + half * 8;
                const float2 rz = *reinterpret_cast<const float2*>(
                    resid + (size_t)i * HID + j);
                float2 o;
                o.x = acc[mi][ni][half * 2 + 0] + bo[j]     + rz.x;
                o.y = acc[mi][ni][half * 2 + 1] + bo[j + 1] + rz.y;
                *reinterpret_cast<float2*>(out + (size_t)i * HID + j) = o;
            }
        }
    }
}

// ======================= bf16 flash attention ================================
// CTA: 64 q-rows x one (b,h), 4 warps x 16 q-rows. 2-stage KV double-buffer.
// XOR-swizzled 128B-stride tiles (proven bit-correct in R12); mask in smem via
// cp.async (R8 style — the __ldg variant regressed). 41.5KB -> 5 CTA/SM target.
#define ATTN_STAGE_BYTES (2 * 64 * 128)                       // K + V per stage
#define ATTN_SMEM_BYTES  (64 * 128 + 2 * ATTN_STAGE_BYTES + 2 * 256)  // 41472
#define LOG2E 1.44269504f

__global__ __launch_bounds__(128)
void attn_bf16(const float* __restrict__ mask)
{
    extern __shared__ char smraw[];
    const uint32_t qB  = smem_u32(smraw);            // Q [64 x 128B], swizzled
    const uint32_t kvB = qB + 64 * 128;              // 2 x (K 8KB + V 8KB)
    const uint32_t mB  = kvB + 2 * ATTN_STAGE_BYTES; // 2 x 256B mask
    float* Msk = reinterpret_cast<float*>(smraw + 64 * 128 + 2 * ATTN_STAGE_BYTES);

    const int qt = blockIdx.x, bh = blockIdx.y;
    const int b  = bh >> 4, h = bh & 15;
    const int q0 = qt * 64;
    const bf16* Qg = g_q + (size_t)bh * SEQ * HDIM + (size_t)q0 * HDIM;
    const bf16* Kg = g_k + (size_t)bh * SEQ * HDIM;
    const bf16* Vg = g_v + (size_t)bh * SEQ * HDIM;
    const float* mk = mask + (size_t)b * SEQ;

    const int t = threadIdx.x, w = t >> 5, lane = t & 31;
    const int g = lane >> 2, tig = lane & 3;
    const int r = lane & 7, hb = (lane >> 3) & 1, hc = lane >> 4;

    // ---- Q tile, swizzled store ----
    #pragma unroll
    for (int u = 0; u < 4; ++u) {
        const int f = t + 128 * u, row = f >> 3, ch = f & 7;
        cp16(qB + row * 128 + ((ch ^ (row & 7)) << 4),
             Qg + (size_t)row * HDIM + ch * 8);
    }
    cp_commit();

    auto kv_prefetch = [&](int kt, int s) {
        const uint32_t sB = kvB + s * ATTN_STAGE_BYTES;
        #pragma unroll
        for (int u = 0; u < 4; ++u) {
            const int f = t + 128 * u, row = f >> 3, ch = f & 7;
            const uint32_t sw = row * 128 + ((ch ^ (row & 7)) << 4);
            cp16(sB + sw,        Kg + (size_t)(kt * 64 + row) * HDIM + ch * 8);
            cp16(sB + 8192 + sw, Vg + (size_t)(kt * 64 + row) * HDIM + ch * 8);
        }
        if (t < 16) cp16(mB + s * 256 + t * 16, mk + kt * 64 + t * 4);
        cp_commit();
    };

    kv_prefetch(0, 0);
    kv_prefetch(1, 1);

    // ---- swizzled fragment offsets (all fragment rows have row&7 == r) ----
    const int baseQ = (w * 16 + r + hb * 8) * 128;            // Q rows
    int baseK[4];
    #pragma unroll
    for (int p = 0; p < 4; ++p) baseK[p] = (p * 16 + hc * 8 + r) * 128;  // K rows
    const int baseV = (r + hb * 8) * 128;                     // V rows (trans)
    int colQV[4], colK[4];
    #pragma unroll
    for (int k4 = 0; k4 < 4; ++k4) {
        colQV[k4] = (((hc + 2 * k4) ^ r) << 4);   // Q cols (kk) / V cols (dj)
        colK[k4]  = (((hb + 2 * k4) ^ r) << 4);   // K cols (kk)
    }

    cp_wait<2>();
    __syncthreads();
    uint32_t qf[4][4];
    #pragma unroll
    for (int kk = 0; kk < 4; ++kk) ldsm_x4(qB + baseQ + colQV[kk], qf[kk]);

    float oacc[8][4];
    #pragma unroll
    for (int di = 0; di < 8; ++di)
        #pragma unroll
        for (int cc = 0; cc < 4; ++cc) oacc[di][cc] = 0.f;
    float lrow[2] = { 0.f, 0.f };
    const float SC = 0.125f * LOG2E;

    #pragma unroll 1
    for (int kt = 0; kt < SEQ / 64; ++kt) {
        if (kt < 31) cp_wait<1>(); else cp_wait<0>();
        __syncthreads();

        const int cur = kt & 1;
        const uint32_t kB = kvB + cur * ATTN_STAGE_BYTES;
        const uint32_t vB = kB + 8192;
        const float* Mc = Msk + cur * 64;

        // ---- S = Q K^T ----
        float sacc[8][4];
        #pragma unroll
        for (int ni = 0; ni < 8; ++ni)
            #pragma unroll
            for (int cc = 0; cc < 4; ++cc) sacc[ni][cc] = 0.f;

        #pragma unroll
        for (int kk = 0; kk < 4; ++kk) {
            uint32_t kb[4][4];
            #pragma unroll
            for (int p = 0; p < 4; ++p) ldsm_x4(kB + baseK[p] + colK[kk], kb[p]);
            #pragma unroll
            for (int ni = 0; ni < 8; ++ni)
                mma_bf16(sacc[ni], qf[kk],
                         kb[ni >> 1][(ni & 1) * 2], kb[ni >> 1][(ni & 1) * 2 + 1]);
        }

        // ---- softmax numerator (log2 domain, fixed reference; mask via smem) ----
        float mm[8][2];
        #pragma unroll
        for (int ni = 0; ni < 8; ++ni) {
            mm[ni][0] = Mc[ni * 8 + 2 * tig]     * LOG2E;
            mm[ni][1] = Mc[ni * 8 + 2 * tig + 1] * LOG2E;
        }
        #pragma unroll
        for (int rr = 0; rr < 2; ++rr) {
            float rs = 0.f;
            #pragma unroll
            for (int ni = 0; ni < 8; ++ni)
                #pragma unroll
                for (int cc = 0; cc < 2; ++cc) {
                    float v = fminf(fmaf(sacc[ni][rr * 2 + cc], SC, mm[ni][cc]), 80.f);
                    const float p = exp2f(v);
                    sacc[ni][rr * 2 + cc] = p;
                    rs += p;
                }
            rs += __shfl_xor_sync(0xffffffffu, rs, 1);
            rs += __shfl_xor_sync(0xffffffffu, rs, 2);
            lrow[rr] += rs;
        }

        // ---- O += P V  (S C-frags repacked as PV A-frags, V via ldsm.trans) ----
        #pragma unroll
        for (int kk = 0; kk < 4; ++kk) {
            uint32_t a[4], vt[4][4];
            a[0] = packbf(sacc[2 * kk][0],     sacc[2 * kk][1]);
            a[1] = packbf(sacc[2 * kk][2],     sacc[2 * kk][3]);
            a[2] = packbf(sacc[2 * kk + 1][0], sacc[2 * kk + 1][1]);
            a[3] = packbf(sacc[2 * kk + 1][2], sacc[2 * kk + 1][3]);
            #pragma unroll
            for (int dj = 0; dj < 4; ++dj)
                ldsm_x4_t(vB + baseV + kk * 2048 + colQV[dj], vt[dj]);
            #pragma unroll
            for (int di = 0; di < 8; ++di)
                mma_bf16(oacc[di], a,
                         vt[di >> 1][(di & 1) * 2], vt[di >> 1][(di & 1) * 2 + 1]);
        }

        __syncthreads();
        if (kt + 2 < 32) kv_prefetch(kt + 2, cur);
    }

    // ---- epilogue: ctx bf16 [B,S,H], column block h*64 ----
    const float inv0 = 1.0f / lrow[0];
    const float inv1 = 1.0f / lrow[1];
    const int row0 = q0 + w * 16 + g;
    bf16* base0 = g_ctx + ((size_t)(b * SEQ + row0)) * HID + h * 64;
    bf16* base1 = g_ctx + ((size_t)(b * SEQ + row0 + 8)) * HID + h * 64;
    #pragma unroll
    for (int di = 0; di < 8; ++di) {
        const int c = di * 8 + 2 * tig;
        *reinterpret_cast<bf162*>(base0 + c) =
            __floats2bfloat162_rn(oacc[di][0] * inv0, oacc[di][1] * inv0);
        *reinterpret_cast<bf162*>(base1 + c) =
            __floats2bfloat162_rn(oacc[di][2] * inv1, oacc[di][3] * inv1);
    }
}

// ================================ launch =====================================
extern "C" void kernel_launch(void* const* d_in, const int* in_sizes, int n_in,
                              void* d_out, int out_size)
{
    const float* hs    = (const float*)d_in[0];
    const float* mask  = (const float*)d_in[1];
    const float* wq    = (const float*)d_in[2];
    const float* bq    = (const float*)d_in[3];
    const float* wk    = (const float*)d_in[4];
    const float* bk    = (const float*)d_in[5];
    const float* wv    = (const float*)d_in[6];
    const float* bv    = (const float*)d_in[7];
    const float* wo    = (const float*)d_in[8];
    const float* bo    = (const float*)d_in[9];
    const float* gamma = (const float*)d_in[10];
    const float* beta  = (const float*)d_in[11];
    float* out = (float*)d_out;

    cudaFuncSetAttribute(gemm_qkv, cudaFuncAttributeMaxDynamicSharedMemorySize,
                         GEMM_SMEM_BYTES);
    cudaFuncSetAttribute(gemm_out, cudaFuncAttributeMaxDynamicSharedMemorySize,
                         GEMM_SMEM_BYTES);
    cudaFuncSetAttribute(attn_bf16, cudaFuncAttributeMaxDynamicSharedMemorySize,
                         ATTN_SMEM_BYTES);

    // 0+1. fused: LayerNorm + weight rounding
    prologue<<<TOK + 2048, 256>>>(hs, gamma, beta, wq, wk, wv, wo);

    // 2. fused Q/K/V projections (R8 8-warp config)
    dim3 gq(HID / 128, TOK / 128, 3);
    gemm_qkv<<<gq, 256, GEMM_SMEM_BYTES>>>(bq, bk, bv);

    // 3. attention (64-row q-tiles, swizzled KV, smem mask)
    dim3 ga(SEQ / 64, BATCH * NHEAD);   // (32, 32) = 1024 CTAs
    attn_bf16<<<ga, 128, ATTN_SMEM_BYTES>>>(mask);

    // 4. output projection + bias + residual
    dim3 gg(HID / 128, TOK / 128);
    gemm_out<<<gg, 256, GEMM_SMEM_BYTES>>>(bo, hs, out);
}

// round 17
// speedup vs baseline: 1.2566x; 1.0905x over previous
#include <cuda_runtime.h>
#include <cuda_bf16.h>
#include <math.h>
#include <stdint.h>

#define BATCH 2
#define SEQ   2048
#define HID   1024
#define NHEAD 16
#define HDIM  64
#define TOK   (BATCH*SEQ)
#define EPS_LN 1e-12f

typedef __nv_bfloat16  bf16;
typedef __nv_bfloat162 bf162;

// ---------------- scratch (device globals; no runtime allocation) ------------
__device__ bf16 g_xln[TOK * HID];      // LN output (bf16)
__device__ bf16 g_q[TOK * HID];        // Q [B,NH,S,HD]
__device__ bf16 g_k[TOK * HID];        // K [B,NH,S,HD]
__device__ bf16 g_v[TOK * HID];        // V [B,NH,S,HD]
__device__ bf16 g_ctx[TOK * HID];      // attention ctx [B,S,H]
__device__ bf16 g_wb[4 * HID * HID];   // bf16 weights: wq wk wv wo

// ---------------- helpers ----------------------------------------------------
__device__ __forceinline__ uint32_t smem_u32(const void* p) {
    return (uint32_t)__cvta_generic_to_shared(p);
}
__device__ __forceinline__ void ldsm_x4(uint32_t addr, uint32_t* r) {
    asm volatile("ldmatrix.sync.aligned.m8n8.x4.shared.b16 {%0,%1,%2,%3}, [%4];"
                 : "=r"(r[0]), "=r"(r[1]), "=r"(r[2]), "=r"(r[3]) : "r"(addr));
}
__device__ __forceinline__ void ldsm_x4_t(uint32_t addr, uint32_t* r) {
    asm volatile("ldmatrix.sync.aligned.m8n8.x4.trans.shared.b16 {%0,%1,%2,%3}, [%4];"
                 : "=r"(r[0]), "=r"(r[1]), "=r"(r[2]), "=r"(r[3]) : "r"(addr));
}
__device__ __forceinline__ void cp16(uint32_t dst, const void* src) {
    asm volatile("cp.async.cg.shared.global [%0], [%1], 16;" :: "r"(dst), "l"(src));
}
__device__ __forceinline__ void cp_commit() { asm volatile("cp.async.commit_group;"); }
template<int N> __device__ __forceinline__ void cp_wait() {
    asm volatile("cp.async.wait_group %0;" :: "n"(N));
}
__device__ __forceinline__ void mma_bf16(float* c, const uint32_t* a,
                                         uint32_t b0, uint32_t b1) {
    asm volatile(
        "mma.sync.aligned.m16n8k16.row.col.f32.bf16.bf16.f32 "
        "{%0,%1,%2,%3}, {%4,%5,%6,%7}, {%8,%9}, {%0,%1,%2,%3};"
        : "+f"(c[0]), "+f"(c[1]), "+f"(c[2]), "+f"(c[3])
        : "r"(a[0]), "r"(a[1]), "r"(a[2]), "r"(a[3]), "r"(b0), "r"(b1));
}
__device__ __forceinline__ uint32_t packbf(float x, float y) {
    bf162 t = __floats2bfloat162_rn(x, y);
    return *reinterpret_cast<uint32_t*>(&t);
}

// ============ fused prologue: LN (blocks 0..4095) + weight rounding ==========
__global__ __launch_bounds__(256)
void prologue(const float* __restrict__ x,
              const float* __restrict__ gamma,
              const float* __restrict__ beta,
              const float* __restrict__ wq, const float* __restrict__ wk,
              const float* __restrict__ wv, const float* __restrict__ wo)
{
    const int t = threadIdx.x;
    if (blockIdx.x < TOK) {
        const int row = blockIdx.x;
        float4 v = reinterpret_cast<const float4*>(x + (size_t)row * HID)[t];

        float s1 = v.x + v.y + v.z + v.w;
        float s2 = v.x*v.x + v.y*v.y + v.z*v.z + v.w*v.w;
        #pragma unroll
        for (int o = 16; o; o >>= 1) {
            s1 += __shfl_xor_sync(0xffffffffu, s1, o);
            s2 += __shfl_xor_sync(0xffffffffu, s2, o);
        }
        __shared__ float red1[8], red2[8];
        const int wid = t >> 5, lane = t & 31;
        if (lane == 0) { red1[wid] = s1; red2[wid] = s2; }
        __syncthreads();
        float tot = 0.f, tot2 = 0.f;
        #pragma unroll
        for (int i = 0; i < 8; i++) { tot += red1[i]; tot2 += red2[i]; }

        const float mu   = tot * (1.0f / HID);
        const float var  = tot2 * (1.0f / HID) - mu * mu;
        const float rstd = rsqrtf(var + EPS_LN);

        const float4 g = reinterpret_cast<const float4*>(gamma)[t];
        const float4 b = reinterpret_cast<const float4*>(beta)[t];
        bf162* out2 = reinterpret_cast<bf162*>(g_xln + (size_t)row * HID) + 2 * t;
        out2[0] = __floats2bfloat162_rn((v.x - mu) * rstd * g.x + b.x,
                                        (v.y - mu) * rstd * g.y + b.y);
        out2[1] = __floats2bfloat162_rn((v.z - mu) * rstd * g.z + b.z,
                                        (v.w - mu) * rstd * g.w + b.w);
    } else {
        const int idx = blockIdx.x - TOK;
        const int m   = idx >> 9;
        const float* src = (m == 0) ? wq : (m == 1) ? wk : (m == 2) ? wv : wo;
        bf16* dst = g_wb + (size_t)m * HID * HID;
        const int e = (idx & 511) * 2048 + t * 8;
        float4 v0 = *reinterpret_cast<const float4*>(src + e);
        float4 v1 = *reinterpret_cast<const float4*>(src + e + 4);
        bf162* d2 = reinterpret_cast<bf162*>(dst + e);
        d2[0] = __floats2bfloat162_rn(v0.x, v0.y);
        d2[1] = __floats2bfloat162_rn(v0.z, v0.w);
        d2[2] = __floats2bfloat162_rn(v1.x, v1.y);
        d2[3] = __floats2bfloat162_rn(v1.z, v1.w);
    }
}

// ================= bf16 GEMM (NT), CTA 64x128, 4 warps =======================
// Warp tile 64x32 (identical per-warp code to R8). XOR-swizzled 128B rows,
// K-tile 64, 2-stage double buffer. 48KB smem + 108 regs -> 4 CTA/SM.
#define G2_STAGE 24576                     // A 8KB + B 16KB
#define G2_SMEM  (2 * G2_STAGE)            // 49152

__device__ __forceinline__ void g2_prefetch(
    uint32_t stB, const bf16* __restrict__ A, const bf16* __restrict__ B,
    int bm0, int bn0, int kt, int t)
{
    // A: 64 rows x 8 chunks = 512 cp16
    #pragma unroll
    for (int u = 0; u < 4; ++u) {
        const int f = t + 128 * u, row = f >> 3, ch = f & 7;
        cp16(stB + row * 128 + ((ch ^ (row & 7)) << 4),
             A + (size_t)(bm0 + row) * HID + kt * 64 + ch * 8);
    }
    // B: 128 rows x 8 chunks = 1024 cp16
    #pragma unroll
    for (int u = 0; u < 8; ++u) {
        const int f = t + 128 * u, row = f >> 3, ch = f & 7;
        cp16(stB + 8192 + row * 128 + ((ch ^ (row & 7)) << 4),
             B + (size_t)(bn0 + row) * HID + kt * 64 + ch * 8);
    }
    cp_commit();
}

__device__ __forceinline__ void g2_compute(
    uint32_t stB, const int* baseA, const int* baseB,
    const int* colA, const int* colB, float acc[4][4][4])
{
    #pragma unroll
    for (int kk = 0; kk < 4; ++kk) {
        uint32_t a[4][4], b[2][4];
        #pragma unroll
        for (int mi = 0; mi < 4; ++mi)
            ldsm_x4(stB + baseA[mi] + colA[kk], a[mi]);
        #pragma unroll
        for (int p = 0; p < 2; ++p)
            ldsm_x4(stB + 8192 + baseB[p] + colB[kk], b[p]);
        #pragma unroll
        for (int mi = 0; mi < 4; ++mi)
            #pragma unroll
            for (int ni = 0; ni < 4; ++ni)
                mma_bf16(acc[mi][ni], a[mi],
                         b[ni >> 1][(ni & 1) * 2], b[ni >> 1][(ni & 1) * 2 + 1]);
    }
}

__device__ __forceinline__ void g2_mainloop(
    const bf16* __restrict__ Ag, const bf16* __restrict__ Bg,
    int bm0, int bn0, int t, const int* baseA, const int* baseB,
    const int* colA, const int* colB, uint32_t smb, float acc[4][4][4])
{
    g2_prefetch(smb,            Ag, Bg, bm0, bn0, 0, t);
    g2_prefetch(smb + G2_STAGE, Ag, Bg, bm0, bn0, 1, t);
    #pragma unroll 1
    for (int kt = 0; kt < 16; ++kt) {
        if (kt < 15) cp_wait<1>(); else cp_wait<0>();
        __syncthreads();
        const uint32_t stB = smb + (kt & 1) * G2_STAGE;
        g2_compute(stB, baseA, baseB, colA, colB, acc);
        __syncthreads();
        if (kt + 2 < 16) g2_prefetch(stB, Ag, Bg, bm0, bn0, kt + 2, t);
    }
}

// QKV projection: z selects weight/bias/output. Out layout [B,NH,S,HD] bf16.
__global__ __launch_bounds__(128)
void gemm_qkv(const float* __restrict__ bq, const float* __restrict__ bk,
              const float* __restrict__ bv)
{
    extern __shared__ char smraw[];
    const uint32_t smb = smem_u32(smraw);

    const int z = blockIdx.z;
    const bf16* W = g_wb + (size_t)z * HID * HID;
    const float* bias = (z == 0) ? bq : (z == 1) ? bk : bv;
    bf16* out = (z == 0) ? g_q : (z == 1) ? g_k : g_v;

    const int t = threadIdx.x, w = t >> 5, lane = t & 31;
    const int r = lane & 7, hb = (lane >> 3) & 1, hc = lane >> 4;
    const int bm0 = blockIdx.y * 64, bn0 = blockIdx.x * 128;
    const int wn = w * 32;

    int baseA[4], baseB[2], colA[4], colB[4];
    #pragma unroll
    for (int mi = 0; mi < 4; ++mi) baseA[mi] = (mi * 16 + r + hb * 8) * 128;
    #pragma unroll
    for (int p = 0; p < 2; ++p)    baseB[p]  = (wn + p * 16 + hc * 8 + r) * 128;
    #pragma unroll
    for (int k4 = 0; k4 < 4; ++k4) {
        colA[k4] = (((hc + 2 * k4) ^ r) << 4);
        colB[k4] = (((hb + 2 * k4) ^ r) << 4);
    }

    float acc[4][4][4];
    #pragma unroll
    for (int mi = 0; mi < 4; ++mi)
        #pragma unroll
        for (int ni = 0; ni < 4; ++ni)
            #pragma unroll
            for (int cc = 0; cc < 4; ++cc) acc[mi][ni][cc] = 0.f;

    g2_mainloop(g_xln, W, bm0, bn0, t, baseA, baseB, colA, colB, smb, acc);

    const int g = lane >> 2, tig = lane & 3;
    #pragma unroll
    for (int mi = 0; mi < 4; ++mi) {
        #pragma unroll
        for (int ni = 0; ni < 4; ++ni) {
            const int j = bn0 + wn + ni * 8 + 2 * tig;
            const int h = j >> 6, d = j & 63;
            #pragma unroll
            for (int half = 0; half < 2; ++half) {
                const int i = bm0 + mi * 16 + g + half * 8;
                const int bb = i >> 11, s = i & 2047;
                const float v0 = acc[mi][ni][half * 2 + 0] + bias[j];
                const float v1 = acc[mi][ni][half * 2 + 1] + bias[j + 1];
                *reinterpret_cast<bf162*>(
                    out + (((size_t)(bb * NHEAD + h)) * SEQ + s) * HDIM + d) =
                    __floats2bfloat162_rn(v0, v1);
            }
        }
    }
}

// O projection + bias + residual (fp32 out)
__global__ __launch_bounds__(128)
void gemm_out(const float* __restrict__ bo, const float* __restrict__ resid,
              float* __restrict__ out)
{
    extern __shared__ char smraw[];
    const uint32_t smb = smem_u32(smraw);
    const bf16* W = g_wb + (size_t)3 * HID * HID;

    const int t = threadIdx.x, w = t >> 5, lane = t & 31;
    const int r = lane & 7, hb = (lane >> 3) & 1, hc = lane >> 4;
    const int bm0 = blockIdx.y * 64, bn0 = blockIdx.x * 128;
    const int wn = w * 32;

    int baseA[4], baseB[2], colA[4], colB[4];
    #pragma unroll
    for (int mi = 0; mi < 4; ++mi) baseA[mi] = (mi * 16 + r + hb * 8) * 128;
    #pragma unroll
    for (int p = 0; p < 2; ++p)    baseB[p]  = (wn + p * 16 + hc * 8 + r) * 128;
    #pragma unroll
    for (int k4 = 0; k4 < 4; ++k4) {
        colA[k4] = (((hc + 2 * k4) ^ r) << 4);
        colB[k4] = (((hb + 2 * k4) ^ r) << 4);
    }

    float acc[4][4][4];
    #pragma unroll
    for (int mi = 0; mi < 4; ++mi)
        #pragma unroll
        for (int ni = 0; ni < 4; ++ni)
            #pragma unroll
            for (int cc = 0; cc < 4; ++cc) acc[mi][ni][cc] = 0.f;

    g2_mainloop(g_ctx, W, bm0, bn0, t, baseA, baseB, colA, colB, smb, acc);

    const int g = lane >> 2, tig = lane & 3;
    #pragma unroll
    for (int mi = 0; mi < 4; ++mi) {
        #pragma unroll
        for (int ni = 0; ni < 4; ++ni) {
            const int j = bn0 + wn + ni * 8 + 2 * tig;
            #pragma unroll
            for (int half = 0; half < 2; ++half) {
                const int i = bm0 + mi * 16 + g + half * 8;
                const float2 rz = *reinterpret_cast<const float2*>(
                    resid + (size_t)i * HID + j);
                float2 o;
                o.x = acc[mi][ni][half * 2 + 0] + bo[j]     + rz.x;
                o.y = acc[mi][ni][half * 2 + 1] + bo[j + 1] + rz.y;
                *reinterpret_cast<float2*>(out + (size_t)i * HID + j) = o;
            }
        }
    }
}

// ======================= bf16 flash attention (R14, unchanged) ===============
#define ATTN_STAGE_BYTES (2 * 64 * 128)
#define ATTN_SMEM_BYTES  (64 * 128 + 2 * ATTN_STAGE_BYTES + 2 * 256)  // 41472
#define LOG2E 1.44269504f

__global__ __launch_bounds__(128)
void attn_bf16(const float* __restrict__ mask)
{
    extern __shared__ char smraw[];
    const uint32_t qB  = smem_u32(smraw);
    const uint32_t kvB = qB + 64 * 128;
    const uint32_t mB  = kvB + 2 * ATTN_STAGE_BYTES;
    float* Msk = reinterpret_cast<float*>(smraw + 64 * 128 + 2 * ATTN_STAGE_BYTES);

    const int qt = blockIdx.x, bh = blockIdx.y;
    const int b  = bh >> 4, h = bh & 15;
    const int q0 = qt * 64;
    const bf16* Qg = g_q + (size_t)bh * SEQ * HDIM + (size_t)q0 * HDIM;
    const bf16* Kg = g_k + (size_t)bh * SEQ * HDIM;
    const bf16* Vg = g_v + (size_t)bh * SEQ * HDIM;
    const float* mk = mask + (size_t)b * SEQ;

    const int t = threadIdx.x, w = t >> 5, lane = t & 31;
    const int g = lane >> 2, tig = lane & 3;
    const int r = lane & 7, hb = (lane >> 3) & 1, hc = lane >> 4;

    #pragma unroll
    for (int u = 0; u < 4; ++u) {
        const int f = t + 128 * u, row = f >> 3, ch = f & 7;
        cp16(qB + row * 128 + ((ch ^ (row & 7)) << 4),
             Qg + (size_t)row * HDIM + ch * 8);
    }
    cp_commit();

    auto kv_prefetch = [&](int kt, int s) {
        const uint32_t sB = kvB + s * ATTN_STAGE_BYTES;
        #pragma unroll
        for (int u = 0; u < 4; ++u) {
            const int f = t + 128 * u, row = f >> 3, ch = f & 7;
            const uint32_t sw = row * 128 + ((ch ^ (row & 7)) << 4);
            cp16(sB + sw,        Kg + (size_t)(kt * 64 + row) * HDIM + ch * 8);
            cp16(sB + 8192 + sw, Vg + (size_t)(kt * 64 + row) * HDIM + ch * 8);
        }
        if (t < 16) cp16(mB + s * 256 + t * 16, mk + kt * 64 + t * 4);
        cp_commit();
    };

    kv_prefetch(0, 0);
    kv_prefetch(1, 1);

    const int baseQ = (w * 16 + r + hb * 8) * 128;
    int baseK[4];
    #pragma unroll
    for (int p = 0; p < 4; ++p) baseK[p] = (p * 16 + hc * 8 + r) * 128;
    const int baseV = (r + hb * 8) * 128;
    int colQV[4], colK[4];
    #pragma unroll
    for (int k4 = 0; k4 < 4; ++k4) {
        colQV[k4] = (((hc + 2 * k4) ^ r) << 4);
        colK[k4]  = (((hb + 2 * k4) ^ r) << 4);
    }

    cp_wait<2>();
    __syncthreads();
    uint32_t qf[4][4];
    #pragma unroll
    for (int kk = 0; kk < 4; ++kk) ldsm_x4(qB + baseQ + colQV[kk], qf[kk]);

    float oacc[8][4];
    #pragma unroll
    for (int di = 0; di < 8; ++di)
        #pragma unroll
        for (int cc = 0; cc < 4; ++cc) oacc[di][cc] = 0.f;
    float lrow[2] = { 0.f, 0.f };
    const float SC = 0.125f * LOG2E;

    #pragma unroll 1
    for (int kt = 0; kt < SEQ / 64; ++kt) {
        if (kt < 31) cp_wait<1>(); else cp_wait<0>();
        __syncthreads();

        const int cur = kt & 1;
        const uint32_t kB = kvB + cur * ATTN_STAGE_BYTES;
        const uint32_t vB = kB + 8192;
        const float* Mc = Msk + cur * 64;

        float sacc[8][4];
        #pragma unroll
        for (int ni = 0; ni < 8; ++ni)
            #pragma unroll
            for (int cc = 0; cc < 4; ++cc) sacc[ni][cc] = 0.f;

        #pragma unroll
        for (int kk = 0; kk < 4; ++kk) {
            uint32_t kb[4][4];
            #pragma unroll
            for (int p = 0; p < 4; ++p) ldsm_x4(kB + baseK[p] + colK[kk], kb[p]);
            #pragma unroll
            for (int ni = 0; ni < 8; ++ni)
                mma_bf16(sacc[ni], qf[kk],
                         kb[ni >> 1][(ni & 1) * 2], kb[ni >> 1][(ni & 1) * 2 + 1]);
        }

        float mm[8][2];
        #pragma unroll
        for (int ni = 0; ni < 8; ++ni) {
            mm[ni][0] = Mc[ni * 8 + 2 * tig]     * LOG2E;
            mm[ni][1] = Mc[ni * 8 + 2 * tig + 1] * LOG2E;
        }
        #pragma unroll
        for (int rr = 0; rr < 2; ++rr) {
            float rs = 0.f;
            #pragma unroll
            for (int ni = 0; ni < 8; ++ni)
                #pragma unroll
                for (int cc = 0; cc < 2; ++cc) {
                    float v = fminf(fmaf(sacc[ni][rr * 2 + cc], SC, mm[ni][cc]), 80.f);
                    const float p = exp2f(v);
                    sacc[ni][rr * 2 + cc] = p;
                    rs += p;
                }
            rs += __shfl_xor_sync(0xffffffffu, rs, 1);
            rs += __shfl_xor_sync(0xffffffffu, rs, 2);
            lrow[rr] += rs;
        }

        #pragma unroll
        for (int kk = 0; kk < 4; ++kk) {
            uint32_t a[4], vt[4][4];
            a[0] = packbf(sacc[2 * kk][0],     sacc[2 * kk][1]);
            a[1] = packbf(sacc[2 * kk][2],     sacc[2 * kk][3]);
            a[2] = packbf(sacc[2 * kk + 1][0], sacc[2 * kk + 1][1]);
            a[3] = packbf(sacc[2 * kk + 1][2], sacc[2 * kk + 1][3]);
            #pragma unroll
            for (int dj = 0; dj < 4; ++dj)
                ldsm_x4_t(vB + baseV + kk * 2048 + colQV[dj], vt[dj]);
            #pragma unroll
            for (int di = 0; di < 8; ++di)
                mma_bf16(oacc[di], a,
                         vt[di >> 1][(di & 1) * 2], vt[di >> 1][(di & 1) * 2 + 1]);
        }

        __syncthreads();
        if (kt + 2 < 32) kv_prefetch(kt + 2, cur);
    }

    const float inv0 = 1.0f / lrow[0];
    const float inv1 = 1.0f / lrow[1];
    const int row0 = q0 + w * 16 + g;
    bf16* base0 = g_ctx + ((size_t)(b * SEQ + row0)) * HID + h * 64;
    bf16* base1 = g_ctx + ((size_t)(b * SEQ + row0 + 8)) * HID + h * 64;
    #pragma unroll
    for (int di = 0; di < 8; ++di) {
        const int c = di * 8 + 2 * tig;
        *reinterpret_cast<bf162*>(base0 + c) =
            __floats2bfloat162_rn(oacc[di][0] * inv0, oacc[di][1] * inv0);
        *reinterpret_cast<bf162*>(base1 + c) =
            __floats2bfloat162_rn(oacc[di][2] * inv1, oacc[di][3] * inv1);
    }
}

// ================================ launch =====================================
extern "C" void kernel_launch(void* const* d_in, const int* in_sizes, int n_in,
                              void* d_out, int out_size)
{
    const float* hs    = (const float*)d_in[0];
    const float* mask  = (const float*)d_in[1];
    const float* wq    = (const float*)d_in[2];
    const float* bq    = (const float*)d_in[3];
    const float* wk    = (const float*)d_in[4];
    const float* bk    = (const float*)d_in[5];
    const float* wv    = (const float*)d_in[6];
    const float* bv    = (const float*)d_in[7];
    const float* wo    = (const float*)d_in[8];
    const float* bo    = (const float*)d_in[9];
    const float* gamma = (const float*)d_in[10];
    const float* beta  = (const float*)d_in[11];
    float* out = (float*)d_out;

    cudaFuncSetAttribute(gemm_qkv, cudaFuncAttributeMaxDynamicSharedMemorySize,
                         G2_SMEM);
    cudaFuncSetAttribute(gemm_out, cudaFuncAttributeMaxDynamicSharedMemorySize,
                         G2_SMEM);
    cudaFuncSetAttribute(attn_bf16, cudaFuncAttributeMaxDynamicSharedMemorySize,
                         ATTN_SMEM_BYTES);

    // 0+1. fused: LayerNorm + weight rounding
    prologue<<<TOK + 2048, 256>>>(hs, gamma, beta, wq, wk, wv, wo);

    // 2. fused Q/K/V projections (CTA 64x128, 4 warps, 4 CTA/SM)
    dim3 gq(HID / 128, TOK / 64, 3);    // (8, 64, 3)
    gemm_qkv<<<gq, 128, G2_SMEM>>>(bq, bk, bv);

    // 3. attention (R14 config)
    dim3 ga(SEQ / 64, BATCH * NHEAD);   // (32, 32)
    attn_bf16<<<ga, 128, ATTN_SMEM_BYTES>>>(mask);

    // 4. output projection + bias + residual
    dim3 gg(HID / 128, TOK / 64);       // (8, 64)
    gemm_out<<<gg, 128, G2_SMEM>>>(bo, hs, out);
}